// round 15
// baseline (speedup 1.0000x reference)
#include <cuda_runtime.h>
#define TT 2048
#define NCTA 128
#define NTH 448
typedef unsigned long long ull;

__device__ __forceinline__ float losum(ull v){ float lo,hi; asm("mov.b64 {%0,%1}, %2;":"=f"(lo),"=f"(hi):"l"(v)); return lo+hi; }
__device__ __forceinline__ ull ff2(ull a,ull b,ull c){ ull d; asm("fma.rn.f32x2 %0, %1, %2, %3;":"=l"(d):"l"(a),"l"(b),"l"(c)); return d; }
__device__ __forceinline__ float ex2f(float x){ float y; asm("ex2.approx.f32 %0, %1;":"=f"(y):"f"(x)); return y; }
__device__ __forceinline__ float rcpf(float x){ float y; asm("rcp.approx.f32 %0, %1;":"=f"(y):"f"(x)); return y; }
__device__ __forceinline__ float sigm(float x){ return rcpf(1.f+ex2f(-1.4426950408889634f*x)); }
__device__ __forceinline__ float tanh_(float x){ float e=ex2f(2.8853900817779268f*x); return 1.f-2.f*rcpf(e+1.f); }

// L1/L2: 4 gates x 8 batches over this thread's K-eighth (3 or 4 j-chunks),
// 3-round butterfly over 8 sq lanes; lane ends owning batch b==sq.
__device__ __forceinline__ void l18(
    const ulonglong2* __restrict__ wq, const ulonglong2* __restrict__ vp,
    bool four, const float* __restrict__ b4, unsigned mask, int sq,
    float& cc, float& hout)
{
    ull ac[4][8];
#pragma unroll
    for (int g=0; g<4; ++g)
#pragma unroll
        for (int b=0; b<8; ++b) ac[g][b]=0ULL;
#pragma unroll
    for (int jj=0; jj<4; ++jj) {
        if (jj==3 && !four) break;
        ulonglong2 w0=wq[jj*51], w1=wq[jj*51+1326], w2=wq[jj*51+2652], w3=wq[jj*51+3978];
#pragma unroll
        for (int b=0; b<8; ++b) {
            ulonglong2 hv=vp[jj*9+b];
            ac[0][b]=ff2(w0.x,hv.x,ac[0][b]); ac[0][b]=ff2(w0.y,hv.y,ac[0][b]);
            ac[1][b]=ff2(w1.x,hv.x,ac[1][b]); ac[1][b]=ff2(w1.y,hv.y,ac[1][b]);
            ac[2][b]=ff2(w2.x,hv.x,ac[2][b]); ac[2][b]=ff2(w2.y,hv.y,ac[2][b]);
            ac[3][b]=ff2(w3.x,hv.x,ac[3][b]); ac[3][b]=ff2(w3.y,hv.y,ac[3][b]);
        }
    }
    float P[4][8];
#pragma unroll
    for (int g=0; g<4; ++g)
#pragma unroll
        for (int b=0; b<8; ++b) P[g][b]=losum(ac[g][b]);
    const int lb=sq&1, l2=(sq>>1)&1, l3=sq>>2;
#pragma unroll
    for (int g=0; g<4; ++g)
#pragma unroll
        for (int i=0; i<4; ++i) {
            float send=P[g][2*i+(1-lb)], keep=P[g][2*i+lb];
            P[g][i]=keep+__shfl_xor_sync(mask,send,1);
        }
#pragma unroll
    for (int g=0; g<4; ++g)
#pragma unroll
        for (int m=0; m<2; ++m) {
            float send=P[g][2*m+(1-l2)], keep=P[g][2*m+l2];
            P[g][m]=keep+__shfl_xor_sync(mask,send,2);
        }
    float r[4];
#pragma unroll
    for (int g=0; g<4; ++g) {
        float send=P[g][1-l3], keep=P[g][l3];
        r[g]=keep+__shfl_xor_sync(mask,send,4)+b4[g];
    }
    float gi=sigm(r[0]), gf=sigm(r[1]), gg=tanh_(r[2]), go=sigm(r[3]);
    cc=gf*cc+gi*gg;
    hout=go*tanh_(cc);
}

// smem (u2): W0@0 [g][j<14][k] 2856 | W1@2856 [g][ch<26][k] 5304 | W2@8160 5304
// V0@13464 2x126 | V1IN@13716 117 | V1OW@13833 2x117 | V2IN@14067 117 | V2OW@14184 2x117
// WL@14418 26 | BL@14444
#define SMEM_BYTES (14445*16)
__constant__ int CS8[8] = {0,4,7,10,13,17,20,23};   // chunk starts (26 chunks over 8 lanes)

__global__ void __launch_bounds__(NTH,1)
lstm_kernel(const float* __restrict__ inp, const float* __restrict__ tim,
            const float* __restrict__ Wih0,const float* __restrict__ Whh0,
            const float* __restrict__ bih0,const float* __restrict__ bhh0,
            const float* __restrict__ Wih1,const float* __restrict__ Whh1,
            const float* __restrict__ bih1,const float* __restrict__ bhh1,
            const float* __restrict__ Wih2,const float* __restrict__ Whh2,
            const float* __restrict__ bih2,const float* __restrict__ bhh2,
            const float* __restrict__ Wlin,const float* __restrict__ blin,
            float* __restrict__ out)
{
    extern __shared__ float sm[];
    ulonglong2* su=(ulonglong2*)sm;
    const int tid=threadIdx.x;
    const int gb0=blockIdx.x*8;

    for (int i=tid; i<2856*4; i+=NTH) {
        int u=i>>2, e=i&3, g=u/714, rem=u-g*714, j=rem/51, kk=rem-j*51;
        int c=j*4+e, r=g*51+kk; float v=0.f;
        if (c<2) v=Wih0[r*2+c]; else if (c<53) v=Whh0[r*51+(c-2)];
        sm[i]=v;
    }
    for (int i=tid; i<5304*4; i+=NTH) {
        int u=i>>2, e=i&3, g=u/1326, rem=u-g*1326, ch=rem/51, kk=rem-ch*51;
        int c=ch*4+e, r=g*51+kk; float v1=0.f, v2=0.f;
        if (c<51) { v1=Wih1[r*51+c]; v2=Wih2[r*51+c]; }
        else if (c>=52 && c<103) { v1=Whh1[r*51+(c-52)]; v2=Whh2[r*51+(c-52)]; }
        sm[2856*4+i]=v1; sm[8160*4+i]=v2;
    }
    for (int i=tid; i<(14418-13464)*4; i+=NTH) sm[13464*4+i]=0.f;
    for (int i=tid; i<104; i+=NTH) {
        int col=i/52, kk=i-col*52;
        sm[14418*4+i]=(kk<51)?Wlin[col*51+kk]:0.f;
    }
    if (tid<2) sm[14444*4+tid]=blin[tid];
    __syncthreads();
    if (tid>=424 && tid<440) {                      // x(t=0)
        int idx=tid-424, xb=idx&7, sel=idx>>3;
        const float* src=sel?tim:inp;
        sm[(13464+xb)*4+sel]=src[(gb0+xb)*TT];
    }

    const int k=tid>>3, sq=tid&7;
    const bool comp=(tid<408);
    const unsigned mask=(tid<384)?0xFFFFFFFFu:0x00FFFFFFu;

    float b0g[4],b1g[4],b2g[4];
    if (comp) {
#pragma unroll
        for (int g=0; g<4; ++g) {
            int r=g*51+k;
            b0g[g]=bih0[r]+bhh0[r]; b1g[g]=bih1[r]+bhh1[r]; b2g[g]=bih2[r]+bhh2[r];
        }
    }
    const int cs=CS8[sq&7];
    const bool own=(sq>=4), four=((sq&3)==0);
    const int lsl=cs-(own?13:0);
    const ulonglong2* w0p=su+k;
    const ulonglong2* w1p=su+2856+cs*51+k;
    const ulonglong2* w2p=su+8160+cs*51+k;

    // v bases (u2): L1: IN@13716 / OWN@13833(+rp*117); L2: IN@14067 / OWN@14184(+rp*117)
    const int v1s = own ? 13833+lsl*9 : 13716+lsl*9;
    const int v2s = own ? 14184+lsl*9 : 14067+lsl*9;

    const int c0=2+k;
    const int stv0  =(13464+(c0>>2)*9+sq)*4+(c0&3);     // +wp*504
    const int kj    =(k>>2)*9+sq;
    const int stv1in=(13716+kj)*4+(k&3);
    const int stv1ow=(13833+kj)*4+(k&3);                // +wp*468
    const int stv2in=(14067+kj)*4+(k&3);
    const int stv2ow=(14184+kj)*4+(k&3);                // +wp*468

    float cc0=0.f, cc1=0.f, cc2=0.f;
    __syncthreads();

    for (int t=0; t<TT; ++t) {
        const int rp=t&1, wp=1-rp;
        // ---- phase 0: L0 (full-K, 1 batch) | head(t-1) | x(t+1) ----
        if (comp) {
            ull a0[4];
#pragma unroll
            for (int g=0; g<4; ++g) a0[g]=0ULL;
            const ulonglong2* vp=su+13464+rp*126+sq;
#pragma unroll
            for (int jj=0; jj<14; ++jj) {
                ulonglong2 hv=vp[jj*9];
#pragma unroll
                for (int g=0; g<4; ++g) {
                    ulonglong2 wv=w0p[(g*14+jj)*51];
                    a0[g]=ff2(wv.x,hv.x,a0[g]); a0[g]=ff2(wv.y,hv.y,a0[g]);
                }
            }
            float gi=sigm(losum(a0[0])+b0g[0]);
            float gf=sigm(losum(a0[1])+b0g[1]);
            float gg=tanh_(losum(a0[2])+b0g[2]);
            float go=sigm(losum(a0[3])+b0g[3]);
            cc0=gf*cc0+gi*gg;
            float h=go*tanh_(cc0);
            sm[stv0+wp*504]=h;
            sm[stv1in]=h;
        } else if (tid>=408 && tid<424) {
            if (t>0) {
                int idx=tid-408, hb=idx>>1, col=idx&1;
                float acc=sm[14444*4+col];
                const int hbase=(14184+rp*117)*4;
#pragma unroll 1
                for (int kk=0; kk<51; ++kk)
                    acc+=sm[14418*4+col*52+kk]*sm[hbase+((kk>>2)*9+hb)*4+(kk&3)];
                if (col) acc=(acc>30.f)?acc:log1pf(__expf(acc));
                out[((gb0+hb)*TT+(t-1))*2+col]=acc;
            }
        } else if (tid>=424 && tid<440) {
            if (t+1<TT) {
                int idx=tid-424, xb=idx&7, sel=idx>>3;
                const float* src=sel?tim:inp;
                sm[(13464+wp*126+xb)*4+sel]=src[(gb0+xb)*TT+t+1];
            }
        }
        __syncthreads();
        // ---- phase 1: L1 ----
        if (comp) {
            float h;
            l18(w1p, su+(own?v1s+rp*117:v1s), four, b1g, mask, sq, cc1, h);
            sm[stv1ow+wp*468]=h;
            sm[stv2in]=h;
        }
        __syncthreads();
        // ---- phase 2: L2 ----
        if (comp) {
            float h;
            l18(w2p, su+(own?v2s+rp*117:v2s), four, b2g, mask, sq, cc2, h);
            sm[stv2ow+wp*468]=h;
        }
        __syncthreads();
    }
    // final head t=TT-1 (h2 in buffer (TT&1)=0)
    if (tid>=408 && tid<424) {
        int idx=tid-408, hb=idx>>1, col=idx&1;
        float acc=sm[14444*4+col];
        const int hbase=(14184+(TT&1)*117)*4;
#pragma unroll 1
        for (int kk=0; kk<51; ++kk)
            acc+=sm[14418*4+col*52+kk]*sm[hbase+((kk>>2)*9+hb)*4+(kk&3)];
        if (col) acc=(acc>30.f)?acc:log1pf(__expf(acc));
        out[((gb0+hb)*TT+(TT-1))*2+col]=acc;
    }
}

extern "C" void kernel_launch(void* const* d_in, const int* in_sizes, int n_in,
                              void* d_out, int out_size)
{
    static bool attr_set=false;
    if (!attr_set) {
        cudaFuncSetAttribute(lstm_kernel, cudaFuncAttributeMaxDynamicSharedMemorySize, SMEM_BYTES);
        attr_set=true;
    }
    lstm_kernel<<<NCTA, NTH, SMEM_BYTES>>>(
        (const float*)d_in[0],  (const float*)d_in[1],
        (const float*)d_in[2],  (const float*)d_in[3],
        (const float*)d_in[4],  (const float*)d_in[5],
        (const float*)d_in[6],  (const float*)d_in[7],
        (const float*)d_in[8],  (const float*)d_in[9],
        (const float*)d_in[10], (const float*)d_in[11],
        (const float*)d_in[12], (const float*)d_in[13],
        (const float*)d_in[14], (const float*)d_in[15],
        (float*)d_out);
}

// round 16
// speedup vs baseline: 5.6630x; 5.6630x over previous
#include <cuda_runtime.h>
#define TT 2048
#define NCTA 128
#define NTH 256
typedef unsigned long long ull;

__device__ __forceinline__ float losum(ull v){ float lo,hi; asm("mov.b64 {%0,%1}, %2;":"=f"(lo),"=f"(hi):"l"(v)); return lo+hi; }
__device__ __forceinline__ ull ff2(ull a,ull b,ull c){ ull d; asm("fma.rn.f32x2 %0, %1, %2, %3;":"=l"(d):"l"(a),"l"(b),"l"(c)); return d; }
__device__ __forceinline__ float ex2f(float x){ float y; asm("ex2.approx.f32 %0, %1;":"=f"(y):"f"(x)); return y; }
__device__ __forceinline__ float rcpf(float x){ float y; asm("rcp.approx.f32 %0, %1;":"=f"(y):"f"(x)); return y; }
__device__ __forceinline__ float sigm(float x){ return rcpf(1.f+ex2f(-1.4426950408889634f*x)); }
__device__ __forceinline__ float tanh_(float x){ float e=ex2f(2.8853900817779268f*x); return 1.f-2.f*rcpf(e+1.f); }

// 4 gates x 8 batches over this thread's K-quarter; 2-round butterfly over 4 sq
// lanes; lane ends owning batches 2*sq, 2*sq+1.
__device__ __forceinline__ void l12(
    const ulonglong2* __restrict__ wq, const ulonglong2* __restrict__ vp,
    int nj7, const float* __restrict__ b4, unsigned mask, int s0, int s1,
    float* __restrict__ cc, float* __restrict__ hout)
{
    ull ac[4][8];
#pragma unroll
    for (int g=0; g<4; ++g)
#pragma unroll
        for (int b=0; b<8; ++b) ac[g][b]=0ULL;
#pragma unroll
    for (int jj=0; jj<7; ++jj) {
        if (jj==6 && !nj7) break;
        ulonglong2 w0=wq[jj*51], w1=wq[jj*51+1326], w2=wq[jj*51+2652], w3=wq[jj*51+3978];
#pragma unroll
        for (int b=0; b<8; ++b) {
            ulonglong2 hv=vp[jj*9+b];
            ac[0][b]=ff2(w0.x,hv.x,ac[0][b]); ac[0][b]=ff2(w0.y,hv.y,ac[0][b]);
            ac[1][b]=ff2(w1.x,hv.x,ac[1][b]); ac[1][b]=ff2(w1.y,hv.y,ac[1][b]);
            ac[2][b]=ff2(w2.x,hv.x,ac[2][b]); ac[2][b]=ff2(w2.y,hv.y,ac[2][b]);
            ac[3][b]=ff2(w3.x,hv.x,ac[3][b]); ac[3][b]=ff2(w3.y,hv.y,ac[3][b]);
        }
    }
    float q[4][4];
#pragma unroll
    for (int g=0; g<4; ++g)
#pragma unroll
        for (int i=0; i<4; ++i) {
            int m=i>>1, e=i&1;
            float av=losum(ac[g][4*m+e]), bv=losum(ac[g][4*m+e+2]);
            float send=s0?av:bv, keep=s0?bv:av;
            q[g][i]=keep+__shfl_xor_sync(mask,send,1);
        }
#pragma unroll
    for (int e=0; e<2; ++e) {
        float r[4];
#pragma unroll
        for (int g=0; g<4; ++g) {
            float av=q[g][e], bv=q[g][2+e];
            float send=s1?av:bv, keep=s1?bv:av;
            r[g]=keep+__shfl_xor_sync(mask,send,2)+b4[g];
        }
        float gi=sigm(r[0]), gf=sigm(r[1]), gg=tanh_(r[2]), go=sigm(r[3]);
        cc[e]=gf*cc[e]+gi*gg;
        hout[e]=go*tanh_(cc[e]);
    }
}

// smem (u2): W0@0 2856 | W1@2856 5304 | W2@8160 5304
// VX@13464 2x8 | V1IN@13480 2x117 | V1OW@13714 2x117 | V2IN@13948 2x117 | V2OW@14182 2x117
// WL@14416 26 | BL@14442 1
#define SMEM_BYTES (14443*16)

__global__ void __launch_bounds__(NTH,1)
lstm_kernel(const float* __restrict__ inp, const float* __restrict__ tim,
            const float* __restrict__ Wih0,const float* __restrict__ Whh0,
            const float* __restrict__ bih0,const float* __restrict__ bhh0,
            const float* __restrict__ Wih1,const float* __restrict__ Whh1,
            const float* __restrict__ bih1,const float* __restrict__ bhh1,
            const float* __restrict__ Wih2,const float* __restrict__ Whh2,
            const float* __restrict__ bih2,const float* __restrict__ bhh2,
            const float* __restrict__ Wlin,const float* __restrict__ blin,
            float* __restrict__ out)
{
    extern __shared__ float sm[];
    ulonglong2* su=(ulonglong2*)sm;
    const int tid=threadIdx.x;
    const int gb0=blockIdx.x*8;

    // W0: cols [x0,x1,0,0, h0(51), 0] (h0 at col 4+kk -> aligned with V1IN f4s)
    for (int i=tid; i<2856*4; i+=NTH) {
        int u=i>>2, e=i&3, g=u/714, rem=u-g*714, j=rem/51, kk=rem-j*51;
        int c=j*4+e, r=g*51+kk; float v=0.f;
        if (c<2) v=Wih0[r*2+c]; else if (c>=4 && c<55) v=Whh0[r*51+(c-4)];
        sm[i]=v;
    }
    for (int i=tid; i<5304*4; i+=NTH) {
        int u=i>>2, e=i&3, g=u/1326, rem=u-g*1326, ch=rem/51, kk=rem-ch*51;
        int c=ch*4+e, r=g*51+kk; float v1=0.f, v2=0.f;
        if (c<51) { v1=Wih1[r*51+c]; v2=Wih2[r*51+c]; }
        else if (c>=52 && c<103) { v1=Whh1[r*51+(c-52)]; v2=Whh2[r*51+(c-52)]; }
        sm[2856*4+i]=v1; sm[8160*4+i]=v2;
    }
    for (int i=tid; i<(14416-13464)*4; i+=NTH) sm[13464*4+i]=0.f;
    for (int i=tid; i<104; i+=NTH) {
        int col=i/52, kk=i-col*52;
        sm[14416*4+i]=(kk<51)?Wlin[col*51+kk]:0.f;
    }
    if (tid<2) sm[14442*4+tid]=blin[tid];
    __syncthreads();
    if (tid>=240) {                                  // x(0) into VX buf 0
        int idx=tid-240, xb=idx&7, sel=idx>>3;
        const float* src=sel?tim:inp;
        sm[(13464+xb)*4+sel]=src[(gb0+xb)*TT];
    }

    const int k=tid>>2, sq=tid&3, s0=sq&1, s1=sq>>1;
    const bool comp=(tid<204);
    const unsigned mask=(tid<192)?0xFFFFFFFFu:0x00000FFFu;

    float b0g[4],b1g[4],b2g[4];
    if (comp) {
#pragma unroll
        for (int g=0; g<4; ++g) {
            int r=g*51+k;
            b0g[g]=bih0[r]+bhh0[r]; b1g[g]=bih1[r]+bhh1[r]; b2g[g]=bih2[r]+bhh2[r];
        }
    }
    const int qofs=s1*663+s0*357;
    const ulonglong2* w0p=su+k;
    const ulonglong2* w1p=su+2856+qofs+k;
    const ulonglong2* w2p=su+8160+qofs+k;
    const int nj7=(s0==0);
    const int v1base=(s1?13714:13480)+s0*63;         // + rp*117
    const int v2base=(s1?14182:13948)+s0*63;         // + rp*117

    const int kj=(k>>2)*9+2*sq;
    const int stv1in=(13480+kj)*4+(k&3);             // + wp*468 + e*4
    const int stv1ow=(13714+kj)*4+(k&3);
    const int stv2in=(13948+kj)*4+(k&3);
    const int stv2ow=(14182+kj)*4+(k&3);

    float cc0[2]={0.f,0.f}, cc1[2]={0.f,0.f}, cc2[2]={0.f,0.f};
    __syncthreads();

    // wavefront: tick s runs L0(s), L1(s-1), L2(s-2); ONE barrier per tick
    for (int s=0; s<TT+2; ++s) {
        const int rp=s&1, wp=1-rp;
        if (comp) {
            if (s<TT) {                              // ---- L0(s): full-K, 2 batches ----
                ull a0[4][2];
#pragma unroll
                for (int g=0; g<4; ++g) { a0[g][0]=0ULL; a0[g][1]=0ULL; }
                const ulonglong2* vx=su+13464+rp*8+2*sq;
                ulonglong2 hva=vx[0], hvb=vx[1];
#pragma unroll
                for (int g=0; g<4; ++g) {
                    ulonglong2 wv=w0p[g*714];
                    a0[g][0]=ff2(wv.x,hva.x,a0[g][0]); a0[g][0]=ff2(wv.y,hva.y,a0[g][0]);
                    a0[g][1]=ff2(wv.x,hvb.x,a0[g][1]); a0[g][1]=ff2(wv.y,hvb.y,a0[g][1]);
                }
                const ulonglong2* v1r=su+13480+rp*117+2*sq;
#pragma unroll
                for (int jj=1; jj<14; ++jj) {
                    hva=v1r[(jj-1)*9]; hvb=v1r[(jj-1)*9+1];
#pragma unroll
                    for (int g=0; g<4; ++g) {
                        ulonglong2 wv=w0p[(g*14+jj)*51];
                        a0[g][0]=ff2(wv.x,hva.x,a0[g][0]); a0[g][0]=ff2(wv.y,hva.y,a0[g][0]);
                        a0[g][1]=ff2(wv.x,hvb.x,a0[g][1]); a0[g][1]=ff2(wv.y,hvb.y,a0[g][1]);
                    }
                }
#pragma unroll
                for (int e=0; e<2; ++e) {
                    float gi=sigm(losum(a0[0][e])+b0g[0]);
                    float gf=sigm(losum(a0[1][e])+b0g[1]);
                    float gg=tanh_(losum(a0[2][e])+b0g[2]);
                    float go=sigm(losum(a0[3][e])+b0g[3]);
                    cc0[e]=gf*cc0[e]+gi*gg;
                    sm[stv1in+wp*468+e*4]=go*tanh_(cc0[e]);
                }
            }
            if (s>=1 && s<=TT) {                     // ---- L1(s-1) ----
                float h[2];
                l12(w1p, su+v1base+rp*117, nj7, b1g, mask, s0, s1, cc1, h);
                sm[stv1ow+wp*468]=h[0]; sm[stv1ow+wp*468+4]=h[1];
                sm[stv2in+wp*468]=h[0]; sm[stv2in+wp*468+4]=h[1];
            }
            if (s>=2) {                              // ---- L2(s-2) ----
                float h[2];
                l12(w2p, su+v2base+rp*117, nj7, b2g, mask, s0, s1, cc2, h);
                sm[stv2ow+wp*468]=h[0]; sm[stv2ow+wp*468+4]=h[1];
            }
        } else if (tid>=224 && tid<240) {
            if (s>=3) {                              // ---- head: out(s-3) ----
                int idx=tid-224, hb=idx>>1, col=idx&1;
                float acc=sm[14442*4+col];
                const int hbase=(14182+rp*117)*4;
#pragma unroll 1
                for (int kk=0; kk<51; ++kk)
                    acc+=sm[14416*4+col*52+kk]*sm[hbase+((kk>>2)*9+hb)*4+(kk&3)];
                if (col) acc=(acc>30.f)?acc:log1pf(__expf(acc));
                out[((gb0+hb)*TT+(s-3))*2+col]=acc;
            }
        } else if (tid>=240) {
            if (s+1<TT) {                            // ---- x(s+1) prefetch ----
                int idx=tid-240, xb=idx&7, sel=idx>>3;
                const float* src=sel?tim:inp;
                sm[(13464+wp*8+xb)*4+sel]=src[(gb0+xb)*TT+s+1];
            }
        }
        __syncthreads();
    }
    // out(TT-1): h2(TT-1) written at tick TT+1 into buffer wp=0
    if (tid>=224 && tid<240) {
        int idx=tid-224, hb=idx>>1, col=idx&1;
        float acc=sm[14442*4+col];
        const int hbase=14182*4;
#pragma unroll 1
        for (int kk=0; kk<51; ++kk)
            acc+=sm[14416*4+col*52+kk]*sm[hbase+((kk>>2)*9+hb)*4+(kk&3)];
        if (col) acc=(acc>30.f)?acc:log1pf(__expf(acc));
        out[((gb0+hb)*TT+(TT-1))*2+col]=acc;
    }
}

extern "C" void kernel_launch(void* const* d_in, const int* in_sizes, int n_in,
                              void* d_out, int out_size)
{
    static bool attr_set=false;
    if (!attr_set) {
        cudaFuncSetAttribute(lstm_kernel, cudaFuncAttributeMaxDynamicSharedMemorySize, SMEM_BYTES);
        attr_set=true;
    }
    lstm_kernel<<<NCTA, NTH, SMEM_BYTES>>>(
        (const float*)d_in[0],  (const float*)d_in[1],
        (const float*)d_in[2],  (const float*)d_in[3],
        (const float*)d_in[4],  (const float*)d_in[5],
        (const float*)d_in[6],  (const float*)d_in[7],
        (const float*)d_in[8],  (const float*)d_in[9],
        (const float*)d_in[10], (const float*)d_in[11],
        (const float*)d_in[12], (const float*)d_in[13],
        (const float*)d_in[14], (const float*)d_in[15],
        (float*)d_out);
}